// round 1
// baseline (speedup 1.0000x reference)
#include <cuda_runtime.h>
#include <math.h>

#define TOTAL 65536
#define DMODEL 512
#define EQKV   1536
#define NGRAPH 1024
#define NPG    64
#define NHEAD  8
#define HD     64
#define PADROW 65   // smem row pitch for 64-wide tiles

// Scratch (sanctioned __device__ globals; no runtime allocation)
__device__ float g_qkv[(size_t)TOTAL * EQKV];   // [65536][1536] q|k|v packed
__device__ float g_ctx[(size_t)TOTAL * DMODEL]; // [65536][512]
__device__ float g_att[(size_t)TOTAL * DMODEL]; // [65536][512]

// ---------------------------------------------------------------------------
// C[M,N] = A[M,K] * B[N,K]^T + bias[N]   (both operands K-contiguous)
// 128x128 block tile, 8x8 micro tile, BK=8, 256 threads.
// ---------------------------------------------------------------------------
__global__ void __launch_bounds__(256) gemm_nt_bias(
    const float* __restrict__ A, const float* __restrict__ B,
    const float* __restrict__ bias, float* __restrict__ C,
    int M, int N, int K)
{
    const int BM = 128, BN = 128, BK = 8;
    __shared__ float As[BK][BM];
    __shared__ float Bs[BK][BN];

    int tid = threadIdx.x;
    int tx = tid & 15;        // 0..15 -> N
    int ty = tid >> 4;        // 0..15 -> M
    int rowBase = blockIdx.y * BM;
    int colBase = blockIdx.x * BN;

    int lr = tid >> 1;        // 0..127 (tile row)
    int ls = (tid & 1) * 4;   // 0 or 4 (k segment)

    const float* Aptr = A + (size_t)(rowBase + lr) * K + ls;
    const float* Bptr = B + (size_t)(colBase + lr) * K + ls;

    float acc[8][8];
    #pragma unroll
    for (int i = 0; i < 8; i++)
        #pragma unroll
        for (int j = 0; j < 8; j++) acc[i][j] = 0.f;

    for (int k0 = 0; k0 < K; k0 += BK) {
        float4 av = *(const float4*)(Aptr + k0);
        float4 bv = *(const float4*)(Bptr + k0);
        As[ls + 0][lr] = av.x; As[ls + 1][lr] = av.y;
        As[ls + 2][lr] = av.z; As[ls + 3][lr] = av.w;
        Bs[ls + 0][lr] = bv.x; Bs[ls + 1][lr] = bv.y;
        Bs[ls + 2][lr] = bv.z; Bs[ls + 3][lr] = bv.w;
        __syncthreads();

        #pragma unroll
        for (int k = 0; k < BK; k++) {
            float a[8], b[8];
            *(float4*)(a)     = *(const float4*)&As[k][ty * 8];
            *(float4*)(a + 4) = *(const float4*)&As[k][ty * 8 + 4];
            *(float4*)(b)     = *(const float4*)&Bs[k][tx * 8];
            *(float4*)(b + 4) = *(const float4*)&Bs[k][tx * 8 + 4];
            #pragma unroll
            for (int i = 0; i < 8; i++)
                #pragma unroll
                for (int j = 0; j < 8; j++)
                    acc[i][j] = fmaf(a[i], b[j], acc[i][j]);
        }
        __syncthreads();
    }

    #pragma unroll
    for (int i = 0; i < 8; i++) {
        size_t r = (size_t)(rowBase + ty * 8 + i);
        #pragma unroll
        for (int j = 0; j < 8; j += 4) {
            int c = colBase + tx * 8 + j;
            float4 o;
            o.x = acc[i][j]     + bias[c];
            o.y = acc[i][j + 1] + bias[c + 1];
            o.z = acc[i][j + 2] + bias[c + 2];
            o.w = acc[i][j + 3] + bias[c + 3];
            *(float4*)&C[r * N + c] = o;
        }
    }
}

// ---------------------------------------------------------------------------
// Per (graph, head) attention: scores = qk^T/8, softmax, ctx = p*v
// grid (NHEAD, NGRAPH), 256 threads, dynamic smem = 4 * 64*PADROW floats
// ---------------------------------------------------------------------------
__global__ void __launch_bounds__(256) attn_kernel()
{
    extern __shared__ float sm[];
    float* Qs = sm;
    float* Ks = sm + 1 * 64 * PADROW;
    float* Vs = sm + 2 * 64 * PADROW;
    float* Ss = sm + 3 * 64 * PADROW;

    int h = blockIdx.x;
    int g = blockIdx.y;
    int tid = threadIdx.x;

    size_t base = (size_t)g * NPG * EQKV + (size_t)h * HD;

    // load q,k,v tiles [64][64]
    for (int i = tid; i < NPG * HD; i += 256) {
        int n = i >> 6, d = i & 63;
        size_t src = base + (size_t)n * EQKV + d;
        Qs[n * PADROW + d] = g_qkv[src];
        Ks[n * PADROW + d] = g_qkv[src + DMODEL];
        Vs[n * PADROW + d] = g_qkv[src + 2 * DMODEL];
    }
    __syncthreads();

    int tx = tid & 15, ty = tid >> 4;
    int n0 = ty * 4, m0 = tx * 4;

    // scores 4x4 micro tile
    {
        float c[4][4];
        #pragma unroll
        for (int i = 0; i < 4; i++)
            #pragma unroll
            for (int j = 0; j < 4; j++) c[i][j] = 0.f;
        for (int d = 0; d < HD; d++) {
            float a[4], b[4];
            #pragma unroll
            for (int i = 0; i < 4; i++) a[i] = Qs[(n0 + i) * PADROW + d];
            #pragma unroll
            for (int j = 0; j < 4; j++) b[j] = Ks[(m0 + j) * PADROW + d];
            #pragma unroll
            for (int i = 0; i < 4; i++)
                #pragma unroll
                for (int j = 0; j < 4; j++)
                    c[i][j] = fmaf(a[i], b[j], c[i][j]);
        }
        #pragma unroll
        for (int i = 0; i < 4; i++)
            #pragma unroll
            for (int j = 0; j < 4; j++)
                Ss[(n0 + i) * PADROW + m0 + j] = c[i][j] * 0.125f;
    }
    __syncthreads();

    // softmax: warp w handles rows w*8 .. w*8+7
    {
        int warp = tid >> 5, lane = tid & 31;
        for (int r = 0; r < 8; r++) {
            int n = warp * 8 + r;
            float v0 = Ss[n * PADROW + lane];
            float v1 = Ss[n * PADROW + lane + 32];
            float mx = fmaxf(v0, v1);
            #pragma unroll
            for (int o = 16; o > 0; o >>= 1)
                mx = fmaxf(mx, __shfl_xor_sync(0xffffffffu, mx, o));
            float e0 = __expf(v0 - mx);
            float e1 = __expf(v1 - mx);
            float s = e0 + e1;
            #pragma unroll
            for (int o = 16; o > 0; o >>= 1)
                s += __shfl_xor_sync(0xffffffffu, s, o);
            float inv = 1.f / s;
            Ss[n * PADROW + lane]      = e0 * inv;
            Ss[n * PADROW + lane + 32] = e1 * inv;
        }
    }
    __syncthreads();

    // ctx = P * V, 4x4 micro tile; cols are head dims
    {
        float c[4][4];
        #pragma unroll
        for (int i = 0; i < 4; i++)
            #pragma unroll
            for (int j = 0; j < 4; j++) c[i][j] = 0.f;
        for (int m = 0; m < NPG; m++) {
            float a[4], b[4];
            #pragma unroll
            for (int i = 0; i < 4; i++) a[i] = Ss[(n0 + i) * PADROW + m];
            #pragma unroll
            for (int j = 0; j < 4; j++) b[j] = Vs[m * PADROW + m0 + j];
            #pragma unroll
            for (int i = 0; i < 4; i++)
                #pragma unroll
                for (int j = 0; j < 4; j++)
                    c[i][j] = fmaf(a[i], b[j], c[i][j]);
        }
        #pragma unroll
        for (int i = 0; i < 4; i++) {
            size_t row = (size_t)(g * NPG + n0 + i) * DMODEL + h * HD + m0;
            #pragma unroll
            for (int j = 0; j < 4; j++)
                g_ctx[row + j] = c[i][j];
        }
    }
}

// ---------------------------------------------------------------------------
// Per-graph gate + reduction: gate_n = sigmoid(attn_n . gw + gb),
// out[g] = sum_n gate_n * attn_n.   grid NGRAPH, 256 threads.
// ---------------------------------------------------------------------------
__global__ void __launch_bounds__(256) gate_reduce(
    const float* __restrict__ gw, const float* __restrict__ gb,
    float* __restrict__ out)
{
    __shared__ float gates[NPG];
    int g = blockIdx.x;
    const float* base = g_att + (size_t)g * NPG * DMODEL;

    int warp = threadIdx.x >> 5, lane = threadIdx.x & 31;
    for (int r = 0; r < 8; r++) {
        int n = warp * 8 + r;
        const float* row = base + (size_t)n * DMODEL;
        float s = 0.f;
        #pragma unroll
        for (int c = 0; c < DMODEL / 32; c++)
            s = fmaf(row[lane + c * 32], gw[lane + c * 32], s);
        #pragma unroll
        for (int o = 16; o > 0; o >>= 1)
            s += __shfl_xor_sync(0xffffffffu, s, o);
        if (lane == 0)
            gates[n] = 1.f / (1.f + __expf(-(s + gb[0])));
    }
    __syncthreads();

    for (int c = threadIdx.x; c < DMODEL; c += 256) {
        float acc = 0.f;
        #pragma unroll 8
        for (int n = 0; n < NPG; n++)
            acc = fmaf(gates[n], base[(size_t)n * DMODEL + c], acc);
        out[(size_t)g * DMODEL + c] = acc;
    }
}

// ---------------------------------------------------------------------------
extern "C" void kernel_launch(void* const* d_in, const int* in_sizes, int n_in,
                              void* d_out, int out_size)
{
    const float* x      = (const float*)d_in[0];
    // d_in[1] = batch (int64), unused: graphs are equal-sized & sorted
    const float* in_w   = (const float*)d_in[2];
    const float* in_b   = (const float*)d_in[3];
    const float* out_w  = (const float*)d_in[4];
    const float* out_b  = (const float*)d_in[5];
    const float* gate_w = (const float*)d_in[6];
    const float* gate_b = (const float*)d_in[7];
    float* out          = (float*)d_out;

    float *qkv, *ctx, *att;
    cudaGetSymbolAddress((void**)&qkv, g_qkv);
    cudaGetSymbolAddress((void**)&ctx, g_ctx);
    cudaGetSymbolAddress((void**)&att, g_att);

    const int smem_attn = 4 * 64 * PADROW * sizeof(float);
    cudaFuncSetAttribute(attn_kernel,
                         cudaFuncAttributeMaxDynamicSharedMemorySize, smem_attn);

    // 1) QKV projection
    gemm_nt_bias<<<dim3(EQKV / 128, TOTAL / 128), 256>>>(
        x, in_w, in_b, qkv, TOTAL, EQKV, DMODEL);

    // 2) per-(graph, head) attention
    attn_kernel<<<dim3(NHEAD, NGRAPH), 256, smem_attn>>>();

    // 3) output projection
    gemm_nt_bias<<<dim3(DMODEL / 128, TOTAL / 128), 256>>>(
        ctx, out_w, out_b, att, TOTAL, DMODEL, DMODEL);

    // 4) gate + per-graph reduction
    gate_reduce<<<NGRAPH, 256>>>(gate_w, gate_b, out);
}

// round 3
// speedup vs baseline: 1.9431x; 1.9431x over previous
#include <cuda_runtime.h>
#include <cuda_bf16.h>
#include <math.h>
#include <stdint.h>

#define TOTAL 65536
#define DMODEL 512
#define EQKV   1536
#define NGRAPH 1024
#define NPG    64
#define NHEAD  8
#define HD     64
#define PADROW 65

// Scratch
__device__ float g_qkv[(size_t)TOTAL * EQKV];
__device__ float g_ctx[(size_t)TOTAL * DMODEL];
__device__ float g_att[(size_t)TOTAL * DMODEL];

__device__ __forceinline__ uint32_t smem_u32(const void* p) {
    uint32_t a;
    asm("{ .reg .u64 t; cvta.to.shared.u64 t, %1; cvt.u32.u64 %0, t; }"
        : "=r"(a) : "l"(p));
    return a;
}

#define LDSM_X4(r0, r1, r2, r3, addr) \
    asm volatile("ldmatrix.sync.aligned.m8n8.x4.shared.b16 {%0,%1,%2,%3}, [%4];" \
        : "=r"(r0), "=r"(r1), "=r"(r2), "=r"(r3) : "r"(addr))
#define LDSM_X2(r0, r1, addr) \
    asm volatile("ldmatrix.sync.aligned.m8n8.x2.shared.b16 {%0,%1}, [%2];" \
        : "=r"(r0), "=r"(r1) : "r"(addr))
#define MMA_BF16(d, a, b) \
    asm volatile("mma.sync.aligned.m16n8k16.row.col.f32.bf16.bf16.f32 " \
        "{%0,%1,%2,%3}, {%4,%5,%6,%7}, {%8,%9}, {%0,%1,%2,%3};" \
        : "+f"((d)[0]), "+f"((d)[1]), "+f"((d)[2]), "+f"((d)[3]) \
        : "r"((a)[0]), "r"((a)[1]), "r"((a)[2]), "r"((a)[3]), \
          "r"((b)[0]), "r"((b)[1]))

__device__ __forceinline__ uint32_t pack_bf2(__nv_bfloat16 lo, __nv_bfloat16 hi) {
    __nv_bfloat162 t(lo, hi);
    return *(uint32_t*)&t;
}
__device__ __forceinline__ void split2(float x, float y, uint32_t& hi, uint32_t& lo) {
    __nv_bfloat16 hx = __float2bfloat16(x), hy = __float2bfloat16(y);
    __nv_bfloat16 lx = __float2bfloat16(x - __bfloat162float(hx));
    __nv_bfloat16 ly = __float2bfloat16(y - __bfloat162float(hy));
    hi = pack_bf2(hx, hy);
    lo = pack_bf2(lx, ly);
}

// ===========================================================================
// Split-bf16 mma.sync GEMM: C[M,N] = A[M,K]*B[N,K]^T + bias[N]
// 128x128 tile, 8 warps (2x4), warp tile 64x32, K-chunk 32.
// smem row pitch 80 bytes (conflict-free ldmatrix).
// ===========================================================================
#define PITCH 80
#define TILEB (128 * PITCH)   // 10240 bytes per matrix

__global__ void __launch_bounds__(256, 1) gemm_mma(
    const float* __restrict__ A, const float* __restrict__ B,
    const float* __restrict__ bias, float* __restrict__ C,
    int N, int K)
{
    __shared__ __align__(16) uint8_t smAh[TILEB];
    __shared__ __align__(16) uint8_t smAl[TILEB];
    __shared__ __align__(16) uint8_t smBh[TILEB];
    __shared__ __align__(16) uint8_t smBl[TILEB];

    const int tid  = threadIdx.x;
    const int wid  = tid >> 5;
    const int lane = tid & 31;
    const int wm   = wid >> 2;      // 0..1 -> M
    const int wn   = wid & 3;       // 0..3 -> N
    const int rowBase = blockIdx.y * 128;
    const int colBase = blockIdx.x * 128;

    const uint32_t aAh = smem_u32(smAh);
    const uint32_t aAl = smem_u32(smAl);
    const uint32_t aBh = smem_u32(smBh);
    const uint32_t aBl = smem_u32(smBl);

    // load mapping: thread -> (row lr, 16-float segment lc)
    const int lr = tid >> 1;
    const int lc = (tid & 1) * 16;
    const float* Aptr = A + (size_t)(rowBase + lr) * K + lc;
    const float* Bptr = B + (size_t)(colBase + lr) * K + lc;

    const int NC = K >> 5;

    float4 pa[4], pb[4];
    #pragma unroll
    for (int i = 0; i < 4; i++) {
        pa[i] = *(const float4*)(Aptr + i * 4);
        pb[i] = *(const float4*)(Bptr + i * 4);
    }

    float acc[4][4][4];
    #pragma unroll
    for (int mf = 0; mf < 4; mf++)
        #pragma unroll
        for (int nf = 0; nf < 4; nf++)
            #pragma unroll
            for (int e = 0; e < 4; e++) acc[mf][nf][e] = 0.f;

    const uint32_t stOff = (uint32_t)lr * PITCH + (uint32_t)lc * 2;

    for (int c = 0; c < NC; c++) {
        // convert + store current chunk
        #pragma unroll
        for (int i = 0; i < 4; i++) {
            uint32_t h0, h1, l0, l1;
            split2(pa[i].x, pa[i].y, h0, l0);
            split2(pa[i].z, pa[i].w, h1, l1);
            *(uint2*)(smAh + stOff + i * 8) = make_uint2(h0, h1);
            *(uint2*)(smAl + stOff + i * 8) = make_uint2(l0, l1);
            split2(pb[i].x, pb[i].y, h0, l0);
            split2(pb[i].z, pb[i].w, h1, l1);
            *(uint2*)(smBh + stOff + i * 8) = make_uint2(h0, h1);
            *(uint2*)(smBl + stOff + i * 8) = make_uint2(l0, l1);
        }
        __syncthreads();

        // prefetch next chunk (overlaps MMAs below)
        if (c + 1 < NC) {
            const int k0 = (c + 1) << 5;
            #pragma unroll
            for (int i = 0; i < 4; i++) {
                pa[i] = *(const float4*)(Aptr + k0 + i * 4);
                pb[i] = *(const float4*)(Bptr + k0 + i * 4);
            }
        }

        #pragma unroll
        for (int ks = 0; ks < 2; ks++) {
            const uint32_t kcol = (uint32_t)ks * 32;
            // B fragments (hi & lo) for all 4 n-frags
            uint32_t bh[4][2], bl[4][2];
            #pragma unroll
            for (int nf = 0; nf < 4; nf++) {
                uint32_t brow = wn * 32 + nf * 8 + (lane & 7);
                uint32_t boff = brow * PITCH + kcol + (((uint32_t)lane >> 3) & 1) * 16;
                LDSM_X2(bh[nf][0], bh[nf][1], aBh + boff);
                LDSM_X2(bl[nf][0], bl[nf][1], aBl + boff);
            }
            #pragma unroll
            for (int mf = 0; mf < 4; mf++) {
                uint32_t arow = wm * 64 + mf * 16 + (lane & 15);
                uint32_t aoff = arow * PITCH + kcol + ((uint32_t)lane >> 4) * 16;
                uint32_t ah[4], al[4];
                LDSM_X4(ah[0], ah[1], ah[2], ah[3], aAh + aoff);
                LDSM_X4(al[0], al[1], al[2], al[3], aAl + aoff);
                #pragma unroll
                for (int nf = 0; nf < 4; nf++) {
                    MMA_BF16(acc[mf][nf], ah, bh[nf]);
                    MMA_BF16(acc[mf][nf], al, bh[nf]);
                    MMA_BF16(acc[mf][nf], ah, bl[nf]);
                }
            }
        }
        __syncthreads();
    }

    // epilogue: c-frag layout m16n8
    const int r0 = rowBase + wm * 64 + (lane >> 2);
    const int c0 = colBase + wn * 32 + (lane & 3) * 2;
    #pragma unroll
    for (int mf = 0; mf < 4; mf++) {
        #pragma unroll
        for (int nf = 0; nf < 4; nf++) {
            int row = r0 + mf * 16;
            int col = c0 + nf * 8;
            float b0 = bias[col], b1 = bias[col + 1];
            *(float2*)&C[(size_t)row * N + col] =
                make_float2(acc[mf][nf][0] + b0, acc[mf][nf][1] + b1);
            *(float2*)&C[(size_t)(row + 8) * N + col] =
                make_float2(acc[mf][nf][2] + b0, acc[mf][nf][3] + b1);
        }
    }
}

// ===========================================================================
// Per (graph, head) attention (fp32)
// ===========================================================================
__global__ void __launch_bounds__(256) attn_kernel()
{
    extern __shared__ float sm[];
    float* Qs = sm;
    float* Ks = sm + 1 * 64 * PADROW;
    float* Vs = sm + 2 * 64 * PADROW;
    float* Ss = sm + 3 * 64 * PADROW;

    int h = blockIdx.x;
    int g = blockIdx.y;
    int tid = threadIdx.x;

    size_t base = (size_t)g * NPG * EQKV + (size_t)h * HD;

    for (int i = tid; i < NPG * HD; i += 256) {
        int n = i >> 6, d = i & 63;
        size_t src = base + (size_t)n * EQKV + d;
        Qs[n * PADROW + d] = g_qkv[src];
        Ks[n * PADROW + d] = g_qkv[src + DMODEL];
        Vs[n * PADROW + d] = g_qkv[src + 2 * DMODEL];
    }
    __syncthreads();

    int tx = tid & 15, ty = tid >> 4;
    int n0 = ty * 4, m0 = tx * 4;

    {
        float c[4][4];
        #pragma unroll
        for (int i = 0; i < 4; i++)
            #pragma unroll
            for (int j = 0; j < 4; j++) c[i][j] = 0.f;
        for (int d = 0; d < HD; d++) {
            float a[4], b[4];
            #pragma unroll
            for (int i = 0; i < 4; i++) a[i] = Qs[(n0 + i) * PADROW + d];
            #pragma unroll
            for (int j = 0; j < 4; j++) b[j] = Ks[(m0 + j) * PADROW + d];
            #pragma unroll
            for (int i = 0; i < 4; i++)
                #pragma unroll
                for (int j = 0; j < 4; j++)
                    c[i][j] = fmaf(a[i], b[j], c[i][j]);
        }
        #pragma unroll
        for (int i = 0; i < 4; i++)
            #pragma unroll
            for (int j = 0; j < 4; j++)
                Ss[(n0 + i) * PADROW + m0 + j] = c[i][j] * 0.125f;
    }
    __syncthreads();

    {
        int warp = tid >> 5, lane = tid & 31;
        for (int r = 0; r < 8; r++) {
            int n = warp * 8 + r;
            float v0 = Ss[n * PADROW + lane];
            float v1 = Ss[n * PADROW + lane + 32];
            float mx = fmaxf(v0, v1);
            #pragma unroll
            for (int o = 16; o > 0; o >>= 1)
                mx = fmaxf(mx, __shfl_xor_sync(0xffffffffu, mx, o));
            float e0 = __expf(v0 - mx);
            float e1 = __expf(v1 - mx);
            float s = e0 + e1;
            #pragma unroll
            for (int o = 16; o > 0; o >>= 1)
                s += __shfl_xor_sync(0xffffffffu, s, o);
            float inv = 1.f / s;
            Ss[n * PADROW + lane]      = e0 * inv;
            Ss[n * PADROW + lane + 32] = e1 * inv;
        }
    }
    __syncthreads();

    {
        float c[4][4];
        #pragma unroll
        for (int i = 0; i < 4; i++)
            #pragma unroll
            for (int j = 0; j < 4; j++) c[i][j] = 0.f;
        for (int m = 0; m < NPG; m++) {
            float a[4], b[4];
            #pragma unroll
            for (int i = 0; i < 4; i++) a[i] = Ss[(n0 + i) * PADROW + m];
            #pragma unroll
            for (int j = 0; j < 4; j++) b[j] = Vs[m * PADROW + m0 + j];
            #pragma unroll
            for (int i = 0; i < 4; i++)
                #pragma unroll
                for (int j = 0; j < 4; j++)
                    c[i][j] = fmaf(a[i], b[j], c[i][j]);
        }
        #pragma unroll
        for (int i = 0; i < 4; i++) {
            size_t row = (size_t)(g * NPG + n0 + i) * DMODEL + h * HD + m0;
            #pragma unroll
            for (int j = 0; j < 4; j++)
                g_ctx[row + j] = c[i][j];
        }
    }
}

// ===========================================================================
// Per-graph gate + reduction
// ===========================================================================
__global__ void __launch_bounds__(256) gate_reduce(
    const float* __restrict__ gw, const float* __restrict__ gb,
    float* __restrict__ out)
{
    __shared__ float gates[NPG];
    int g = blockIdx.x;
    const float* base = g_att + (size_t)g * NPG * DMODEL;

    int warp = threadIdx.x >> 5, lane = threadIdx.x & 31;
    for (int r = 0; r < 8; r++) {
        int n = warp * 8 + r;
        const float* row = base + (size_t)n * DMODEL;
        float s = 0.f;
        #pragma unroll
        for (int c = 0; c < DMODEL / 32; c++)
            s = fmaf(row[lane + c * 32], gw[lane + c * 32], s);
        #pragma unroll
        for (int o = 16; o > 0; o >>= 1)
            s += __shfl_xor_sync(0xffffffffu, s, o);
        if (lane == 0)
            gates[n] = 1.f / (1.f + __expf(-(s + gb[0])));
    }
    __syncthreads();

    for (int c = threadIdx.x; c < DMODEL; c += 256) {
        float acc = 0.f;
        #pragma unroll 8
        for (int n = 0; n < NPG; n++)
            acc = fmaf(gates[n], base[(size_t)n * DMODEL + c], acc);
        out[(size_t)g * DMODEL + c] = acc;
    }
}

// ===========================================================================
extern "C" void kernel_launch(void* const* d_in, const int* in_sizes, int n_in,
                              void* d_out, int out_size)
{
    const float* x      = (const float*)d_in[0];
    const float* in_w   = (const float*)d_in[2];
    const float* in_b   = (const float*)d_in[3];
    const float* out_w  = (const float*)d_in[4];
    const float* out_b  = (const float*)d_in[5];
    const float* gate_w = (const float*)d_in[6];
    const float* gate_b = (const float*)d_in[7];
    float* out          = (float*)d_out;

    float *qkv, *ctx, *att;
    cudaGetSymbolAddress((void**)&qkv, g_qkv);
    cudaGetSymbolAddress((void**)&ctx, g_ctx);
    cudaGetSymbolAddress((void**)&att, g_att);

    const int smem_attn = 4 * 64 * PADROW * sizeof(float);
    cudaFuncSetAttribute(attn_kernel,
                         cudaFuncAttributeMaxDynamicSharedMemorySize, smem_attn);

    // 1) QKV projection: [65536,512] x [1536,512]^T
    gemm_mma<<<dim3(EQKV / 128, TOTAL / 128), 256>>>(
        x, in_w, in_b, qkv, EQKV, DMODEL);

    // 2) per-(graph, head) attention
    attn_kernel<<<dim3(NHEAD, NGRAPH), 256, smem_attn>>>();

    // 3) output projection: [65536,512] x [512,512]^T
    gemm_mma<<<dim3(DMODEL / 128, TOTAL / 128), 256>>>(
        ctx, out_w, out_b, att, DMODEL, DMODEL);

    // 4) gate + per-graph reduction
    gate_reduce<<<NGRAPH, 256>>>(gate_w, gate_b, out);
}